// round 13
// baseline (speedup 1.0000x reference)
#include <cuda_runtime.h>
#include <math.h>
#include <stdint.h>

#define B_    64
#define T_    1000
#define D_    512
#define V_    29
#define L_    200
#define S_    401            // 2*L + 1
#define CBLANK 28
#define LOG2E 1.44269504088896340736f
#define LN2   0.69314718055994530942f
#define ESENT (-(1 << 29))   // integer-exponent sentinel ("-inf")

typedef unsigned long long u64;

// ---------------- device scratch (no allocations allowed) ----------------
__device__ float d_lp[(long)B_ * T_ * V_];   // LINEAR probs p[b][t][v], 7.4 MB
__device__ float d_loss[B_];

__device__ __forceinline__ float ex2f(float x){ float r; asm("ex2.approx.f32 %0, %1;" : "=f"(r) : "f"(x)); return r; }
__device__ __forceinline__ float lg2f(float x){ float r; asm("lg2.approx.f32 %0, %1;" : "=f"(r) : "f"(x)); return r; }

#define FMA2(d, a, b) asm("fma.rn.f32x2 %0, %1, %2, %0;" : "+l"(d) : "l"(a), "l"(b))

// =====================================================================
// Kernel 1: logits = F @ W + b, softmax, write LINEAR probs to d_lp.
// (Proven R10/R12 2-stage structure.) 256 threads, BM=256 rows/block,
// tile 8 rows x 4 cols, FFMA2 over k-pairs; W resident transposed.
// =====================================================================
#define BM2 256
#define WT_STRIDE 516
#define SMEM_GEMM_BYTES 132608

extern __shared__ char smem_dyn[];

__global__ __launch_bounds__(256, 1) void gemm_sm_kernel(
    const float* __restrict__ F, const float* __restrict__ W,
    const float* __restrict__ bias)
{
    float* fbuf = (float*)smem_dyn;
    float* wT   = (float*)(smem_dyn + 65536);
    float* csh  = (float*)(smem_dyn + 131584);
    float* lbuf = fbuf;                         // epilogue reuse

    const int tid = threadIdx.x;
    const long rowBase = (long)blockIdx.x * BM2;
    const uint32_t fsh = (uint32_t)__cvta_generic_to_shared(fbuf);

    auto prefetch = [&](int kci, int st) {
        const uint32_t sbase = fsh + st * 32768u;
#pragma unroll
        for (int m = 0; m < 8; m++) {
            const int q  = tid + 256 * m;
            const int r  = q >> 3;
            const int kq = q & 7;
            const float* src = F + (rowBase + r) * D_ + kci * 32 + kq * 4;
            const uint32_t dst = sbase + (uint32_t)((r * 32 + ((kq ^ ((r >> 3) & 7)) << 2)) * 4);
            asm volatile("cp.async.ca.shared.global [%0], [%1], 16;" :: "r"(dst), "l"(src));
        }
    };

    prefetch(0, 0);
    asm volatile("cp.async.commit_group;");

    for (int idx = tid; idx < 512 * 32; idx += 256) {
        const int k = idx >> 5, c = idx & 31;
        wT[c * WT_STRIDE + k] = (c < V_) ? W[(long)k * V_ + c] : 0.f;
    }

    const int rg = tid >> 3;
    const int cg = tid & 7;
    const int fkey = (rg & 7) << 2;

    float bv[4];
#pragma unroll
    for (int j = 0; j < 4; j++) { int c = cg + 8 * j; bv[j] = (c < V_) ? bias[c] : 0.f; }

    u64 acc[8][4];
#pragma unroll
    for (int i = 0; i < 8; i++)
#pragma unroll
        for (int j = 0; j < 4; j++) acc[i][j] = 0ull;

    for (int kci = 0; kci < 16; kci++) {
        if (kci < 15) prefetch(kci + 1, (kci + 1) & 1);
        asm volatile("cp.async.commit_group;");
        asm volatile("cp.async.wait_group 1;");
        __syncthreads();

        const float* fstage = fbuf + (kci & 1) * 8192;
        const float* wbase  = wT + kci * 32;
#pragma unroll
        for (int kq = 0; kq < 8; kq++) {
            ulonglong2 f[8], w4[4];
#pragma unroll
            for (int i = 0; i < 8; i++)
                f[i] = *reinterpret_cast<const ulonglong2*>(
                    fstage + (rg * 8 + i) * 32 + ((kq << 2) ^ fkey));
#pragma unroll
            for (int j = 0; j < 4; j++)
                w4[j] = *reinterpret_cast<const ulonglong2*>(
                    wbase + (cg + 8 * j) * WT_STRIDE + kq * 4);
#pragma unroll
            for (int i = 0; i < 8; i++)
#pragma unroll
                for (int j = 0; j < 4; j++) FMA2(acc[i][j], f[i].x, w4[j].x);
#pragma unroll
            for (int i = 0; i < 8; i++)
#pragma unroll
                for (int j = 0; j < 4; j++) FMA2(acc[i][j], f[i].y, w4[j].y);
        }
        __syncthreads();
    }

#pragma unroll
    for (int i = 0; i < 8; i++)
#pragma unroll
        for (int j = 0; j < 4; j++) {
            const float lo = __uint_as_float((unsigned)(acc[i][j] & 0xffffffffull));
            const float hi = __uint_as_float((unsigned)(acc[i][j] >> 32));
            lbuf[(rg * 8 + i) * 33 + (cg + 8 * j)] = lo + hi + bv[j];
        }
    __syncthreads();

    {
        const float* r = &lbuf[tid * 33];
        float m = r[0];
#pragma unroll
        for (int v = 1; v < V_; v++) m = fmaxf(m, r[v]);
        float sum = 0.f;
#pragma unroll
        for (int v = 0; v < V_; v++) sum += ex2f((r[v] - m) * LOG2E);
        csh[tid] = m * LOG2E + lg2f(sum);
    }
    __syncthreads();

    // coalesced write of LINEAR probabilities
    float* outp = d_lp + rowBase * V_;
    for (int i = tid; i < BM2 * V_; i += 256) {
        const int row = i / V_;
        const int v   = i - row * V_;
        outp[i] = ex2f(lbuf[row * 33 + v] * LOG2E - csh[row]);
    }
}

// =====================================================================
// Kernel 2: CTC alpha recursion, EXACT LINEAR (mantissa, int-exponent),
// 4 STATES PER THREAD, 2 STEPS PER BARRIER, zero MUFU in the loop.
// 128 threads (4 warps); thread i owns states 4i..4i+3 =
// (blank,label,blank,label) in registers. Per iteration (2 timesteps):
// read thread i-1's top 3 states (2x LDS.128), do 4 own updates (step t),
// 1 redundant virtual update of state 4i-1 (step t), 4 own updates
// (step t+1), store, ONE barrier. All updates are 4-cycle ALU/FMA.
// =====================================================================
struct ME { float m; int E; };
struct PF { float B0, B1, p10, p11, p30, p31, V0; };

__device__ __forceinline__ float mkscale(int d) {
    return __uint_as_float((unsigned)max(d + 127, 0) << 23);
}
__device__ __forceinline__ ME me_renorm(float v, int Em) {
    const unsigned bits = __float_as_uint(v);
    ME r;
    r.E = Em + (int)(bits >> 23) - 127;
    r.m = __uint_as_float((bits & 0x007fffffu) | 0x3f800000u);
    return r;
}
__device__ __forceinline__ ME me_split(float v) { return me_renorm(v, 0); }
// blank update: p * (a + b)
__device__ __forceinline__ ME upd2(ME a, ME b, float p) {
    const int Em = max(a.E, b.E);
    const float sum = fmaf(a.m, mkscale(a.E - Em), b.m * mkscale(b.E - Em));
    return me_renorm(p * sum, Em);
}
// label update: p * (a + b + (sk ? c : 0))
__device__ __forceinline__ ME upd3(ME a, ME b, ME c, bool sk, float p) {
    const int Ec = sk ? c.E : ESENT;
    const int Em = max(a.E, max(b.E, Ec));
    const float sum = fmaf(a.m, mkscale(a.E - Em),
                      fmaf(b.m, mkscale(b.E - Em), c.m * mkscale(Ec - Em)));
    return me_renorm(p * sum, Em);
}

__global__ __launch_bounds__(128) void ctc_kernel(
    const int* __restrict__ labels, const int* __restrict__ flens,
    const int* __restrict__ llens)
{
    __shared__ float4 pm[2][132];       // [.][i+1] = mantissas of states 4i..4i+3
    __shared__ float4 pe[2][132];       // [.][i+1] = exponents (int as float bits)
    __shared__ int    lab_sh[L_];
    __shared__ float  afin[520];

    const int b    = blockIdx.x;
    const int tid  = threadIdx.x;
    const int flen = flens[b];
    const int llen = llens[b];

    for (int k = tid; k < L_; k += 128) lab_sh[k] = labels[b * L_ + k];
    if (tid == 0) {
        const float4 mpad = make_float4(1.f, 1.f, 1.f, 1.f);
        const float  es   = __int_as_float(ESENT);
        const float4 epad = make_float4(es, es, es, es);
        pm[0][0] = mpad; pm[1][0] = mpad;
        pe[0][0] = epad; pe[1][0] = epad;
    }
    __syncthreads();

    const int i  = tid;
    const int j1 = min(2 * i,     L_ - 1);
    const int j3 = min(2 * i + 1, L_ - 1);
    const int jv = min(max(2 * i - 1, 0), L_ - 1);
    const int e1 = lab_sh[j1];
    const int e3 = lab_sh[j3];
    const int eV = lab_sh[jv];
    const bool skip1 = (i >= 1) && (e1 != lab_sh[j1 - 1]);
    const bool skip3 = (e3 != lab_sh[j3 - 1]);              // j3 >= 1 always
    const bool skipv = (i >= 1) && (eV != lab_sh[jv - 1]);

    const float* lpb = d_lp + (long)b * T_ * V_;

    // t = 0 init
    ME a0 = {1.f, ESENT}, a1 = {1.f, ESENT}, a2 = {1.f, ESENT}, a3 = {1.f, ESENT};
    if (i == 0) { a0 = me_split(lpb[CBLANK]); a1 = me_split(lpb[e1]); }
    pm[0][i + 1] = make_float4(a0.m, a1.m, a2.m, a3.m);
    pe[0][i + 1] = make_float4(__int_as_float(a0.E), __int_as_float(a1.E),
                               __int_as_float(a2.E), __int_as_float(a3.E));

    auto loadPF = [&](int tt) {
        PF f;
        const int r0 = min(tt,     T_ - 1) * V_;
        const int r1 = min(tt + 1, T_ - 1) * V_;
        f.B0 = lpb[r0 + CBLANK]; f.p10 = lpb[r0 + e1];
        f.p30 = lpb[r0 + e3];    f.V0  = lpb[r0 + eV];
        f.B1 = lpb[r1 + CBLANK]; f.p11 = lpb[r1 + e1]; f.p31 = lpb[r1 + e3];
        return f;
    };

    PF f0 = loadPF(1);
    PF f1 = loadPF(3);
    __syncthreads();

    int cur = 0;
    int t = 1;

#define CTC_ITER(F) do {                                                         \
    const float4 nm  = pm[cur][i];                                               \
    const float4 neb = pe[cur][i];                                               \
    const ME n1 = {nm.y, __float_as_int(neb.y)};   /* state 4i-3 */              \
    const ME n2 = {nm.z, __float_as_int(neb.z)};   /* state 4i-2 */              \
    const ME n3 = {nm.w, __float_as_int(neb.w)};   /* state 4i-1 */              \
    /* step t */                                                                 \
    const ME b0 = upd2(a0, n3, F.B0);                                            \
    const ME l1 = upd3(a1, a0, n3, skip1, F.p10);                                \
    const ME b2 = upd2(a2, a1, F.B0);                                            \
    const ME l3 = upd3(a3, a2, a1, skip3, F.p30);                                \
    const ME vv = upd3(n3, n2, n1, skipv, F.V0);   /* virtual 4i-1 at t */       \
    /* step t+1 */                                                               \
    a0 = upd2(b0, vv, F.B1);                                                     \
    a1 = upd3(l1, b0, vv, skip1, F.p11);                                         \
    a2 = upd2(b2, l1, F.B1);                                                     \
    a3 = upd3(l3, b2, l1, skip3, F.p31);                                         \
    pm[cur ^ 1][i + 1] = make_float4(a0.m, a1.m, a2.m, a3.m);                    \
    pe[cur ^ 1][i + 1] = make_float4(__int_as_float(a0.E), __int_as_float(a1.E), \
                                     __int_as_float(a2.E), __int_as_float(a3.E));\
    cur ^= 1;                                                                    \
    __syncthreads();                                                             \
    t += 2;                                                                      \
} while (0)

    while (t + 3 < flen) {
        CTC_ITER(f0); f0 = loadPF(t + 2);
        CTC_ITER(f1); f1 = loadPF(t + 2);
    }
    while (t + 1 < flen) {
        CTC_ITER(f0);
        f0 = f1; f1 = loadPF(t + 2);
    }
    if (t < flen) {
        // single leftover step
        const float4 nm  = pm[cur][i];
        const float4 neb = pe[cur][i];
        const ME n3 = {nm.w, __float_as_int(neb.w)};
        const ME b0 = upd2(a0, n3, f0.B0);
        const ME l1 = upd3(a1, a0, n3, skip1, f0.p10);
        const ME b2 = upd2(a2, a1, f0.B0);
        const ME l3 = upd3(a3, a2, a1, skip3, f0.p30);
        a0 = b0; a1 = l1; a2 = b2; a3 = l3;
    }
#undef CTC_ITER

    __syncthreads();
    afin[4 * i + 0] = (float)a0.E + lg2f(a0.m);
    afin[4 * i + 1] = (float)a1.E + lg2f(a1.m);
    afin[4 * i + 2] = (float)a2.E + lg2f(a2.m);
    afin[4 * i + 3] = (float)a3.E + lg2f(a3.m);
    __syncthreads();

    if (tid == 0) {
        const float l1 = afin[2 * llen];        // alpha[2*llen]   (llen >= 50)
        const float l2 = afin[2 * llen - 1];    // alpha[2*llen-1]
        const float mx = fmaxf(l1, l2), mn = fminf(l1, l2);
        const float ls = mx + lg2f(1.0f + ex2f(mn - mx));
        const float nll = -ls * LN2;
        d_loss[b] = (nll < 5e8f) ? nll / (float)llen : 0.f;
    }
}

// =====================================================================
// Kernel 3: deterministic fixed-order mean of 64 losses
// =====================================================================
__global__ void reduce_kernel(float* __restrict__ out)
{
    const int lane = threadIdx.x;
    float v = d_loss[lane] + d_loss[lane + 32];
#pragma unroll
    for (int o = 16; o > 0; o >>= 1) v += __shfl_down_sync(0xffffffffu, v, o);
    if (lane == 0) out[0] = v * (1.f / (float)B_);
}

// =====================================================================
extern "C" void kernel_launch(void* const* d_in, const int* in_sizes, int n_in,
                              void* d_out, int out_size)
{
    (void)in_sizes; (void)n_in; (void)out_size;
    const float* F      = (const float*)d_in[0];
    const float* W      = (const float*)d_in[1];
    const float* bias   = (const float*)d_in[2];
    const int*   labels = (const int*)d_in[3];
    const int*   flens  = (const int*)d_in[4];
    const int*   llens  = (const int*)d_in[5];
    float* out = (float*)d_out;

    cudaFuncSetAttribute(gemm_sm_kernel,
                         cudaFuncAttributeMaxDynamicSharedMemorySize, SMEM_GEMM_BYTES);

    gemm_sm_kernel<<<(B_ * T_) / BM2, 256, SMEM_GEMM_BYTES>>>(F, W, bias);
    ctc_kernel<<<B_, 128>>>(labels, flens, llens);
    reduce_kernel<<<1, 32>>>(out);
}

// round 14
// speedup vs baseline: 1.1321x; 1.1321x over previous
#include <cuda_runtime.h>
#include <math.h>
#include <stdint.h>

#define B_    64
#define T_    1000
#define D_    512
#define V_    29
#define L_    200
#define CBLANK 28
#define LOG2E 1.44269504088896340736f
#define LN2   0.69314718055994530942f
#define ESENT (-(1 << 29))

#define CHUNK  125           // t-rows per GEMM block
#define NCHUNK 8             // 1000 / 125
#define NGEMM  (NCHUNK * B_) // 512 producer blocks
#define GRID_F (B_ + NGEMM)  // 576 total blocks

typedef unsigned long long u64;

// ---------------- device scratch (no allocations allowed) ----------------
__device__ float d_lp[(long)B_ * T_ * V_];   // LINEAR probs p[b][t][v]
__device__ float d_loss[B_];
__device__ float d_wT[32 * 512];             // transposed W (pre-kernel)
__device__ int   d_flag[NCHUNK * B_];        // [chunk][sample] ready flags

__device__ __forceinline__ float ex2f(float x){ float r; asm("ex2.approx.f32 %0, %1;" : "=f"(r) : "f"(x)); return r; }
__device__ __forceinline__ float lg2f(float x){ float r; asm("lg2.approx.f32 %0, %1;" : "=f"(r) : "f"(x)); return r; }

#define FMA2(d, a, b) asm("fma.rn.f32x2 %0, %1, %2, %0;" : "+l"(d) : "l"(a), "l"(b))

// ---- linear (mantissa, int-exponent) arithmetic (proven in R11/R13) ----
struct ME { float m; int E; };

__device__ __forceinline__ float mkscale(int d) {
    return __uint_as_float((unsigned)max(d + 127, 0) << 23);
}
__device__ __forceinline__ ME me_renorm(float v, int Em) {
    const unsigned bits = __float_as_uint(v);
    ME r;
    r.E = Em + (int)(bits >> 23) - 127;
    r.m = __uint_as_float((bits & 0x007fffffu) | 0x3f800000u);
    return r;
}
__device__ __forceinline__ ME me_split(float v) { return me_renorm(v, 0); }
__device__ __forceinline__ ME upd2(ME a, ME b, float p) {
    const int Em = max(a.E, b.E);
    const float sum = fmaf(a.m, mkscale(a.E - Em), b.m * mkscale(b.E - Em));
    return me_renorm(p * sum, Em);
}
__device__ __forceinline__ ME upd3(ME a, ME b, ME c, bool sk, float p) {
    const int Ec = sk ? c.E : ESENT;
    const int Em = max(a.E, max(b.E, Ec));
    const float sum = fmaf(a.m, mkscale(a.E - Em),
                      fmaf(b.m, mkscale(b.E - Em), c.m * mkscale(Ec - Em)));
    return me_renorm(p * sum, Em);
}

// ---- flag sync helpers ----
__device__ __forceinline__ void set_flag(int idx) {
    asm volatile("st.release.gpu.global.b32 [%0], %1;"
                 :: "l"(d_flag + idx), "r"(1) : "memory");
}
__device__ __forceinline__ int ld_flag(int idx) {
    int f;
    asm volatile("ld.acquire.gpu.global.b32 %0, [%1];"
                 : "=f"(*(float*)&f) : "l"(d_flag + idx) : "memory");
    return f;
}
__device__ __forceinline__ void wait_rows(int b, int row, int& ready) {
    const int need = row / CHUNK;            // chunk containing 'row'
    while (ready <= need) {
        if (ld_flag(ready * B_ + b)) ready++;
        else __nanosleep(128);
    }
}

// =====================================================================
// Pre-kernel: zero flags + transpose W into d_wT[32][512].
// =====================================================================
__global__ __launch_bounds__(128) void pre_kernel(const float* __restrict__ W)
{
    const int bid = blockIdx.x, tid = threadIdx.x;
    if (bid < 32) {
        for (int k = tid; k < 512; k += 128)
            d_wT[bid * 512 + k] = (bid < V_) ? W[k * V_ + bid] : 0.f;
    } else {
        for (int i = tid; i < NCHUNK * B_; i += 128) d_flag[i] = 0;
    }
}

// =====================================================================
// Fused kernel: blocks [0,64) = CTC consumers, [64,576) = GEMM producers.
// 128 threads/block. Dynamic smem 42496B (GEMM needs it all; CTC ~12KB).
// =====================================================================
#define SMEM_FUSED 42496

extern __shared__ char smem_dyn[];

__device__ void gemm_path(const float* __restrict__ F,
                          const float* __restrict__ bias)
{
    float* fbuf = (float*)smem_dyn;                  // 2 x 128x32 f  (32768B)
    float* wt   = (float*)(smem_dyn + 32768);        // 2 x 32x36  f  (9216B)
    float* csh  = (float*)(smem_dyn + 41984);        // 128 f
    float* lbuf = fbuf;                              // epilogue reuse

    const int tid = threadIdx.x;
    const int gb  = blockIdx.x - B_;
    const int c   = gb >> 6;          // chunk index 0..7
    const int b   = gb & 63;          // sample
    const long rowBase = (long)b * T_ + c * CHUNK;
    const uint32_t fsh  = (uint32_t)__cvta_generic_to_shared(fbuf);
    const uint32_t wtsh = (uint32_t)__cvta_generic_to_shared(wt);

    auto prefetch = [&](int kci, int st) {
        const uint32_t sbase = fsh + (uint32_t)st * 16384u;
#pragma unroll
        for (int m = 0; m < 8; m++) {
            const int q  = tid + 128 * m;            // 0..1023
            const int r  = q >> 3;
            const int kq = q & 7;
            long row = rowBase + r;
            if (row > (long)B_ * T_ - 1) row = (long)B_ * T_ - 1;   // tail clamp
            const float* src = F + row * D_ + kci * 32 + kq * 4;
            const uint32_t dst = sbase + (uint32_t)((r * 32 + ((kq ^ ((r >> 3) & 7)) << 2)) * 4);
            asm volatile("cp.async.ca.shared.global [%0], [%1], 16;" :: "r"(dst), "l"(src));
        }
        const uint32_t wbase = wtsh + (uint32_t)st * 4608u;
#pragma unroll
        for (int m = 0; m < 2; m++) {
            const int q   = tid + 128 * m;           // 0..255
            const int col = q >> 3;
            const int kq  = q & 7;
            const float* src = d_wT + col * 512 + kci * 32 + kq * 4;
            const uint32_t dst = wbase + (uint32_t)((col * 36 + kq * 4) * 4);
            asm volatile("cp.async.ca.shared.global [%0], [%1], 16;" :: "r"(dst), "l"(src));
        }
    };

    prefetch(0, 0);
    asm volatile("cp.async.commit_group;");

    const int rg = tid >> 3;          // 0..15 : rows rg*8 + i
    const int cg = tid & 7;           // 0..7  : cols cg + 8*j
    const int fkey = (rg & 7) << 2;

    float bv[4];
#pragma unroll
    for (int j = 0; j < 4; j++) { int cc = cg + 8 * j; bv[j] = (cc < V_) ? bias[cc] : 0.f; }

    u64 acc[8][4];
#pragma unroll
    for (int i = 0; i < 8; i++)
#pragma unroll
        for (int j = 0; j < 4; j++) acc[i][j] = 0ull;

    for (int kci = 0; kci < 16; kci++) {
        if (kci < 15) prefetch(kci + 1, (kci + 1) & 1);
        asm volatile("cp.async.commit_group;");
        asm volatile("cp.async.wait_group 1;");
        __syncthreads();

        const float* fstage = fbuf + (kci & 1) * 4096;
        const float* wstage = wt   + (kci & 1) * 1152;
#pragma unroll
        for (int kq = 0; kq < 8; kq++) {
            ulonglong2 f[8], w4[4];
#pragma unroll
            for (int i = 0; i < 8; i++)
                f[i] = *reinterpret_cast<const ulonglong2*>(
                    fstage + (rg * 8 + i) * 32 + ((kq << 2) ^ fkey));
#pragma unroll
            for (int j = 0; j < 4; j++)
                w4[j] = *reinterpret_cast<const ulonglong2*>(
                    wstage + (cg + 8 * j) * 36 + kq * 4);
#pragma unroll
            for (int i = 0; i < 8; i++)
#pragma unroll
                for (int j = 0; j < 4; j++) FMA2(acc[i][j], f[i].x, w4[j].x);
#pragma unroll
            for (int i = 0; i < 8; i++)
#pragma unroll
                for (int j = 0; j < 4; j++) FMA2(acc[i][j], f[i].y, w4[j].y);
        }
        __syncthreads();
    }

    // epilogue: combine k-pairs, bias, logits to smem [128][33]
#pragma unroll
    for (int i = 0; i < 8; i++)
#pragma unroll
        for (int j = 0; j < 4; j++) {
            const float lo = __uint_as_float((unsigned)(acc[i][j] & 0xffffffffull));
            const float hi = __uint_as_float((unsigned)(acc[i][j] >> 32));
            lbuf[(rg * 8 + i) * 33 + (cg + 8 * j)] = lo + hi + bv[j];
        }
    __syncthreads();

    if (tid < CHUNK) {
        const float* r = &lbuf[tid * 33];
        float m = r[0];
#pragma unroll
        for (int v = 1; v < V_; v++) m = fmaxf(m, r[v]);
        float sum = 0.f;
#pragma unroll
        for (int v = 0; v < V_; v++) sum += ex2f((r[v] - m) * LOG2E);
        csh[tid] = m * LOG2E + lg2f(sum);
    }
    __syncthreads();

    float* outp = d_lp + rowBase * V_;
    for (int i = tid; i < CHUNK * V_; i += 128) {
        const int row = i / V_;
        const int v   = i - row * V_;
        outp[i] = ex2f(lbuf[row * 33 + v] * LOG2E - csh[row]);
    }

    __syncthreads();
    __threadfence();
    if (tid == 0) set_flag(c * B_ + b);
}

struct PFv { float B0, B1, p10, p11, p30, p31, V0; };

__device__ void ctc_path(const int* __restrict__ labels,
                         const int* __restrict__ flens,
                         const int* __restrict__ llens)
{
    float4* pm    = (float4*)smem_dyn;               // [2][132]
    float4* pe    = pm + 2 * 132;                    // [2][132]
    int*    lab_sh = (int*)(pe + 2 * 132);           // [200]
    float*  afin  = (float*)(lab_sh + L_);           // [520]

    const int b    = blockIdx.x;
    const int tid  = threadIdx.x;
    const int flen = flens[b];
    const int llen = llens[b];

    for (int k = tid; k < L_; k += 128) lab_sh[k] = labels[b * L_ + k];
    if (tid == 0) {
        const float4 mpad = make_float4(1.f, 1.f, 1.f, 1.f);
        const float  es   = __int_as_float(ESENT);
        const float4 epad = make_float4(es, es, es, es);
        pm[0] = mpad; pm[132] = mpad;
        pe[0] = epad; pe[132] = epad;
    }
    __syncthreads();

    const int i  = tid;
    const int j1 = min(2 * i,     L_ - 1);
    const int j3 = min(2 * i + 1, L_ - 1);
    const int jv = min(max(2 * i - 1, 0), L_ - 1);
    const int e1 = lab_sh[j1];
    const int e3 = lab_sh[j3];
    const int eV = lab_sh[jv];
    const bool skip1 = (i >= 1) && (e1 != lab_sh[j1 - 1]);
    const bool skip3 = (e3 != lab_sh[j3 - 1]);
    const bool skipv = (i >= 1) && (eV != lab_sh[jv - 1]);

    const float* lpb = d_lp + (long)b * T_ * V_;
    int ready = 0;                                   // confirmed chunks

    auto loadPF = [&](int tt) {
        PFv f;
        const int r0c = min(tt,     T_ - 1);
        const int r1c = min(tt + 1, T_ - 1);
        wait_rows(b, r1c, ready);
        const int r0 = r0c * V_;
        const int r1 = r1c * V_;
        f.B0 = lpb[r0 + CBLANK]; f.p10 = lpb[r0 + e1];
        f.p30 = lpb[r0 + e3];    f.V0  = lpb[r0 + eV];
        f.B1 = lpb[r1 + CBLANK]; f.p11 = lpb[r1 + e1]; f.p31 = lpb[r1 + e3];
        return f;
    };

    // t = 0 init (needs chunk 0)
    wait_rows(b, 0, ready);
    ME a0 = {1.f, ESENT}, a1 = {1.f, ESENT}, a2 = {1.f, ESENT}, a3 = {1.f, ESENT};
    if (i == 0) { a0 = me_split(lpb[CBLANK]); a1 = me_split(lpb[e1]); }
    pm[i + 1] = make_float4(a0.m, a1.m, a2.m, a3.m);
    pe[i + 1] = make_float4(__int_as_float(a0.E), __int_as_float(a1.E),
                            __int_as_float(a2.E), __int_as_float(a3.E));

    PFv f0 = loadPF(1);
    PFv f1 = loadPF(3);
    __syncthreads();

    int cur = 0;
    int t = 1;

#define CTC_ITER(F) do {                                                         \
    const float4 nm  = pm[cur * 132 + i];                                        \
    const float4 neb = pe[cur * 132 + i];                                        \
    const ME n1 = {nm.y, __float_as_int(neb.y)};                                 \
    const ME n2 = {nm.z, __float_as_int(neb.z)};                                 \
    const ME n3 = {nm.w, __float_as_int(neb.w)};                                 \
    const ME b0 = upd2(a0, n3, F.B0);                                            \
    const ME l1 = upd3(a1, a0, n3, skip1, F.p10);                                \
    const ME b2 = upd2(a2, a1, F.B0);                                            \
    const ME l3 = upd3(a3, a2, a1, skip3, F.p30);                                \
    const ME vv = upd3(n3, n2, n1, skipv, F.V0);                                 \
    a0 = upd2(b0, vv, F.B1);                                                     \
    a1 = upd3(l1, b0, vv, skip1, F.p11);                                         \
    a2 = upd2(b2, l1, F.B1);                                                     \
    a3 = upd3(l3, b2, l1, skip3, F.p31);                                         \
    pm[(cur ^ 1) * 132 + i + 1] = make_float4(a0.m, a1.m, a2.m, a3.m);           \
    pe[(cur ^ 1) * 132 + i + 1] = make_float4(                                   \
        __int_as_float(a0.E), __int_as_float(a1.E),                              \
        __int_as_float(a2.E), __int_as_float(a3.E));                             \
    cur ^= 1;                                                                    \
    __syncthreads();                                                             \
    t += 2;                                                                      \
} while (0)

    while (t + 3 < flen) {
        CTC_ITER(f0); f0 = loadPF(t + 2);
        CTC_ITER(f1); f1 = loadPF(t + 2);
    }
    while (t + 1 < flen) {
        CTC_ITER(f0);
        f0 = f1; f1 = loadPF(t + 2);
    }
    if (t < flen) {
        const float4 nm  = pm[cur * 132 + i];
        const float4 neb = pe[cur * 132 + i];
        const ME n3 = {nm.w, __float_as_int(neb.w)};
        const ME b0 = upd2(a0, n3, f0.B0);
        const ME l1 = upd3(a1, a0, n3, skip1, f0.p10);
        const ME b2 = upd2(a2, a1, f0.B0);
        const ME l3 = upd3(a3, a2, a1, skip3, f0.p30);
        a0 = b0; a1 = l1; a2 = b2; a3 = l3;
    }
#undef CTC_ITER

    __syncthreads();
    afin[4 * i + 0] = (float)a0.E + lg2f(a0.m);
    afin[4 * i + 1] = (float)a1.E + lg2f(a1.m);
    afin[4 * i + 2] = (float)a2.E + lg2f(a2.m);
    afin[4 * i + 3] = (float)a3.E + lg2f(a3.m);
    __syncthreads();

    if (tid == 0) {
        const float l1 = afin[2 * llen];
        const float l2 = afin[2 * llen - 1];
        const float mx = fmaxf(l1, l2), mn = fminf(l1, l2);
        const float ls = mx + lg2f(1.0f + ex2f(mn - mx));
        const float nll = -ls * LN2;
        d_loss[b] = (nll < 5e8f) ? nll / (float)llen : 0.f;
    }
}

__global__ __launch_bounds__(128) void fused_kernel(
    const float* __restrict__ F, const float* __restrict__ bias,
    const int* __restrict__ labels, const int* __restrict__ flens,
    const int* __restrict__ llens)
{
    if (blockIdx.x < B_) ctc_path(labels, flens, llens);
    else                 gemm_path(F, bias);
}

// =====================================================================
// reduce: deterministic fixed-order mean of 64 losses
// =====================================================================
__global__ void reduce_kernel(float* __restrict__ out)
{
    const int lane = threadIdx.x;
    float v = d_loss[lane] + d_loss[lane + 32];
#pragma unroll
    for (int o = 16; o > 0; o >>= 1) v += __shfl_down_sync(0xffffffffu, v, o);
    if (lane == 0) out[0] = v * (1.f / (float)B_);
}

// =====================================================================
extern "C" void kernel_launch(void* const* d_in, const int* in_sizes, int n_in,
                              void* d_out, int out_size)
{
    (void)in_sizes; (void)n_in; (void)out_size;
    const float* F      = (const float*)d_in[0];
    const float* W      = (const float*)d_in[1];
    const float* bias   = (const float*)d_in[2];
    const int*   labels = (const int*)d_in[3];
    const int*   flens  = (const int*)d_in[4];
    const int*   llens  = (const int*)d_in[5];
    float* out = (float*)d_out;

    cudaFuncSetAttribute(fused_kernel,
                         cudaFuncAttributeMaxDynamicSharedMemorySize, SMEM_FUSED);

    pre_kernel<<<33, 128>>>(W);
    fused_kernel<<<GRID_F, 128, SMEM_FUSED>>>(F, bias, labels, flens, llens);
    reduce_kernel<<<1, 32>>>(out);
}